// round 15
// baseline (speedup 1.0000x reference)
#include <cuda_runtime.h>
#include <cuda_bf16.h>
#include <math.h>
#include <stdint.h>

// ============================================================================
// CrossAttention, 4 launches total.
//   0) cvt_all: x,y,Wq,Wk,Wv -> bf16  +  zero L      (one kernel, segments)
//   1) proj3:   q=x@Wq, k=y@Wk, v=y@Wv               (one fused launch, 12 slots)
//   2) scores:  E = exp(q k^T / 32) + row-sums L     (no max-sub; scores small)
//   3) pv:      out = (E @ v) / L + x                (fp32 out)
// GEMM core: CTA 128x128, 4 warps, warp tile 64x64, K-tile 64, 3-stage
// cp.async. R15: (a) cp.async burst moved AFTER ks0 MMAs (issue-order bubble),
// (b) co-resident CTA phase stagger (~800 cyc for odd wave-slot CTAs).
// Shapes: B=16, S=2048, IN=1024, DQK=256, DV=1024
// ============================================================================

#define BATCH 16
#define SEQ   2048
#define INDIM 1024
#define DQK   256
#define DV    1024

typedef __nv_bfloat16 bf16;

// scratch
__device__ __align__(16) bf16 g_xb[(size_t)BATCH * SEQ * INDIM];
__device__ __align__(16) bf16 g_yb[(size_t)BATCH * SEQ * INDIM];
__device__ __align__(16) bf16 g_wq[INDIM * DQK];
__device__ __align__(16) bf16 g_wk[INDIM * DQK];
__device__ __align__(16) bf16 g_wv[INDIM * DV];
__device__ __align__(16) bf16 g_qb[(size_t)BATCH * SEQ * DQK];
__device__ __align__(16) bf16 g_kb[(size_t)BATCH * SEQ * DQK];
__device__ __align__(16) bf16 g_vb[(size_t)BATCH * SEQ * DV];
__device__ __align__(16) bf16 g_e [(size_t)BATCH * SEQ * SEQ];
__device__ __align__(16) float g_l[(size_t)BATCH * SEQ];

// ---------------------------------------------------------------------------
// fused convert + L-zero kernel (compile-time segment bounds)
// ---------------------------------------------------------------------------
#define X4_  (BATCH * SEQ * INDIM / 4)  // 8,388,608
#define WQ4_ (INDIM * DQK / 4)          // 65,536
#define WV4_ (INDIM * DV / 4)           // 262,144
#define L4_  (BATCH * SEQ / 4)          // 8,192
#define CVT_TOTAL (2 * X4_ + 2 * WQ4_ + WV4_ + L4_)

__global__ void cvt_all(const float* __restrict__ x,
                        const float* __restrict__ y,
                        const float* __restrict__ Wq,
                        const float* __restrict__ Wk,
                        const float* __restrict__ Wv,
                        bf16* xb, bf16* yb, bf16* wq, bf16* wk, bf16* wv,
                        float* lb) {
    int i = blockIdx.x * blockDim.x + threadIdx.x;
    if (i >= CVT_TOTAL) return;
    if (i >= 2 * X4_ + 2 * WQ4_ + WV4_) {  // zero L
        int j = i - (2 * X4_ + 2 * WQ4_ + WV4_);
        ((float4*)lb)[j] = make_float4(0.f, 0.f, 0.f, 0.f);
        return;
    }
    const float* src;
    bf16* dst;
    int j;
    if (i < X4_) { src = x; dst = xb; j = i; }
    else if (i < 2 * X4_) { src = y; dst = yb; j = i - X4_; }
    else if (i < 2 * X4_ + WQ4_) { src = Wq; dst = wq; j = i - 2 * X4_; }
    else if (i < 2 * X4_ + 2 * WQ4_) { src = Wk; dst = wk; j = i - 2 * X4_ - WQ4_; }
    else { src = Wv; dst = wv; j = i - 2 * X4_ - 2 * WQ4_; }
    float4 f = ((const float4*)src)[j];
    __nv_bfloat162* d = (__nv_bfloat162*)dst + 2 * (size_t)j;
    d[0] = __floats2bfloat162_rn(f.x, f.y);
    d[1] = __floats2bfloat162_rn(f.z, f.w);
}

// ---------------------------------------------------------------------------
// primitives
// ---------------------------------------------------------------------------
__device__ __forceinline__ void ldsm_x4(uint32_t* r, uint32_t addr) {
    asm volatile("ldmatrix.sync.aligned.m8n8.x4.shared.b16 {%0,%1,%2,%3}, [%4];"
                 : "=r"(r[0]), "=r"(r[1]), "=r"(r[2]), "=r"(r[3]) : "r"(addr));
}
__device__ __forceinline__ void ldsm_x4t(uint32_t* r, uint32_t addr) {
    asm volatile(
        "ldmatrix.sync.aligned.m8n8.x4.trans.shared.b16 {%0,%1,%2,%3}, [%4];"
        : "=r"(r[0]), "=r"(r[1]), "=r"(r[2]), "=r"(r[3]) : "r"(addr));
}
__device__ __forceinline__ void mma_bf16(float* c, const uint32_t* a,
                                         const uint32_t* b) {
    asm volatile(
        "mma.sync.aligned.m16n8k16.row.col.f32.bf16.bf16.f32 "
        "{%0,%1,%2,%3}, {%4,%5,%6,%7}, {%8,%9}, {%0,%1,%2,%3};"
        : "+f"(c[0]), "+f"(c[1]), "+f"(c[2]), "+f"(c[3])
        : "r"(a[0]), "r"(a[1]), "r"(a[2]), "r"(a[3]), "r"(b[0]), "r"(b[1]));
}
__device__ __forceinline__ void cp16(uint32_t dst, const void* src) {
    asm volatile("cp.async.cg.shared.global [%0], [%1], 16;"
                 :: "r"(dst), "l"(src));
}

// ---------------------------------------------------------------------------
// shared GEMM mainloop: acc += A[bm:bm+128, :K] * B
//   BKIND 1: B bf16 k-major [K][N]  (ldsm x4 trans)
//   BKIND 2: B bf16 n-major [N][K]  (ldsm x4)
// 128 threads, warp grid 2(m) x 2(n), warp tile 64x64, K-tile 64,
// 3-stage cp.async, fragment double-buffer.
// Per-tile order: sync -> kk0+kk1 ldsm -> ks0 MMAs -> cp.async burst -> ...
// ---------------------------------------------------------------------------
#define SA_STRIDE 72      // [128][64+8]
#define SB_STRIDE_K 136   // [64][128+8]
#define SB_STRIDE_N 72    // [128][64+8]
#define ASZ (128 * SA_STRIDE)   // 9216 elems
#define BSZ (128 * SB_STRIDE_N) // 9216 elems (>= 64*136 = 8704)
#define NSTAGE 3
#define SMEM_BYTES (NSTAGE * (ASZ + BSZ) * 2)   // 110,592 B
#define THREADS 128

template <int BKIND>
__device__ __forceinline__ void gemm_body(
    const bf16* __restrict__ A, const bf16* __restrict__ B,
    int K, int ldb, int bm, int bn, bf16* smem, float acc[4][8][4]) {
    const int t    = threadIdx.x;
    const int lane = t & 31;
    const int warp = t >> 5;
    const int wm   = warp >> 1;
    const int wn   = warp & 1;
    const int l15  = lane & 15;

    // phase stagger: co-resident CTAs (wave slots bid, bid+148) get opposite
    // parity of (slot/148); odd ones delay ~800 cyc so their per-tile barriers
    // run anti-phased instead of locking.
    {
        int slot = blockIdx.x + gridDim.x * (blockIdx.y + gridDim.y * blockIdx.z);
        if ((slot / 148) & 1) {
            float d = 1.0f + lane;
#pragma unroll 1
            for (int i = 0; i < 200; i++)
                asm volatile("add.f32 %0, %0, 0f3F800000;" : "+f"(d));
            if (d == -1.0f) ((volatile bf16*)smem)[0] = (bf16)d;  // keep live
        }
    }

    const uint32_t shA_u = (uint32_t)__cvta_generic_to_shared(smem);
    const uint32_t shB_u =
        (uint32_t)__cvta_generic_to_shared(smem + NSTAGE * ASZ);

    const uint32_t a_off =
        (uint32_t)((wm * 64 + l15) * SA_STRIDE + (lane >> 4) * 8);
    uint32_t b_off;
    if (BKIND == 2) {
        int m = lane >> 3;
        b_off = (uint32_t)((wn * 64 + (m >> 1) * 8 + (lane & 7)) * SB_STRIDE_N +
                           (m & 1) * 8);
    } else {
        b_off = (uint32_t)(l15 * SB_STRIDE_K + wn * 64 + (lane >> 4) * 8);
    }

    const int NT = K >> 6;

    auto issue = [&](int kt, int buf) {
        const int k0 = kt << 6;
#pragma unroll
        for (int c = 0; c < 8; c++) {
            int idx = t + c * THREADS;
            int row = idx >> 3, col = (idx & 7) * 8;
            cp16(shA_u + (buf * ASZ + row * SA_STRIDE + col) * 2,
                 A + (size_t)(bm + row) * K + k0 + col);
        }
        if (BKIND == 1) {
#pragma unroll
            for (int c = 0; c < 8; c++) {
                int idx = t + c * THREADS;
                int kr = idx >> 4, n = (idx & 15) * 8;
                cp16(shB_u + (buf * BSZ + kr * SB_STRIDE_K + n) * 2,
                     B + (size_t)(k0 + kr) * ldb + bn + n);
            }
        } else {
#pragma unroll
            for (int c = 0; c < 8; c++) {
                int idx = t + c * THREADS;
                int row = idx >> 3, col = (idx & 7) * 8;
                cp16(shB_u + (buf * BSZ + row * SB_STRIDE_N + col) * 2,
                     B + (size_t)(bn + row) * ldb + k0 + col);
            }
        }
        asm volatile("cp.async.commit_group;");
    };

    auto load_frag = [&](uint32_t bufA, uint32_t bufB, int kk,
                         uint32_t a[4][4], uint32_t b[8][2]) {
#pragma unroll
        for (int mt = 0; mt < 4; mt++)
            ldsm_x4(a[mt], bufA + (a_off + mt * 16 * SA_STRIDE + kk) * 2);
#pragma unroll
        for (int nt = 0; nt < 8; nt += 2) {
            uint32_t r[4];
            if (BKIND == 2) {
                ldsm_x4(r, bufB + (b_off + nt * 8 * SB_STRIDE_N + kk) * 2);
            } else {
                ldsm_x4t(r, bufB + (b_off + nt * 8 + kk * SB_STRIDE_K) * 2);
            }
            b[nt][0] = r[0]; b[nt][1] = r[1];
            b[nt + 1][0] = r[2]; b[nt + 1][1] = r[3];
        }
    };

    issue(0, 0);
    issue(1, 1);

    for (int kt = 0; kt < NT; kt++) {
        const int buf = kt % 3;
        if (kt + 1 < NT)
            asm volatile("cp.async.wait_group 1;");
        else
            asm volatile("cp.async.wait_group 0;");
        __syncthreads();

        const uint32_t bufA = shA_u + (buf * ASZ) * 2;
        const uint32_t bufB = shB_u + (buf * BSZ) * 2;

        // kk0 fragments first: the asm-volatile order puts MMAs right after
        // the ldsm batches; the cp.async burst is deferred to after ks0's MMAs
        // (race-free: buffer (kt+2)%3 was fully consumed at kt-1).
        uint32_t afrag[2][4][4];
        uint32_t bfrag[2][8][2];
        load_frag(bufA, bufB, 0, afrag[0], bfrag[0]);

#pragma unroll
        for (int ks = 0; ks < 4; ks++) {
            const int cur = ks & 1;
            const int nxt = cur ^ 1;
            if (ks < 3)
                load_frag(bufA, bufB, (ks + 1) * 16, afrag[nxt], bfrag[nxt]);
#pragma unroll
            for (int mt = 0; mt < 4; mt++)
#pragma unroll
                for (int nt = 0; nt < 8; nt++)
                    mma_bf16(acc[mt][nt], afrag[cur][mt], bfrag[cur][nt]);
            if (ks == 0 && kt + 2 < NT) issue(kt + 2, (kt + 2) % 3);
        }
    }
}

// ---------------------------------------------------------------------------
// kernel 1: fused q/k/v projections.
// grid.x in [0,12): 0-1 -> q n-tiles (DQK/128=2), 2-3 -> k n-tiles,
//                   4-11 -> v n-tiles (DV/128=8).
// grid.y = M/128 m-tiles.
// ---------------------------------------------------------------------------
__global__ void __launch_bounds__(THREADS, 2)
proj3_kernel(const bf16* __restrict__ xb, const bf16* __restrict__ yb,
             const bf16* __restrict__ wq, const bf16* __restrict__ wk,
             const bf16* __restrict__ wv,
             bf16* qb, bf16* kb, bf16* vb) {
    extern __shared__ __align__(16) bf16 smem[];
    const int gx = blockIdx.x;
    const int bm = blockIdx.y * 128;

    const bf16 *A, *B;
    bf16* C;
    int ldn, bn;
    if (gx < 2)      { A = xb; B = wq; C = qb; ldn = DQK; bn = gx * 128; }
    else if (gx < 4) { A = yb; B = wk; C = kb; ldn = DQK; bn = (gx - 2) * 128; }
    else             { A = yb; B = wv; C = vb; ldn = DV;  bn = (gx - 4) * 128; }

    float acc[4][8][4];
#pragma unroll
    for (int mt = 0; mt < 4; mt++)
#pragma unroll
        for (int nt = 0; nt < 8; nt++)
#pragma unroll
            for (int i = 0; i < 4; i++) acc[mt][nt][i] = 0.0f;

    gemm_body<1>(A, B, INDIM, ldn, bm, bn, smem, acc);

    const int lane = threadIdx.x & 31;
    const int warp = threadIdx.x >> 5;
    const int wm = warp >> 1, wn = warp & 1;
    const int g = lane >> 2, t2 = (lane & 3) * 2;
#pragma unroll
    for (int mt = 0; mt < 4; mt++) {
        int r = bm + wm * 64 + mt * 16 + g;
#pragma unroll
        for (int nt = 0; nt < 8; nt++) {
            int c = bn + wn * 64 + nt * 8 + t2;
            *(__nv_bfloat162*)(C + (size_t)r * ldn + c) =
                __floats2bfloat162_rn(acc[mt][nt][0], acc[mt][nt][1]);
            *(__nv_bfloat162*)(C + (size_t)(r + 8) * ldn + c) =
                __floats2bfloat162_rn(acc[mt][nt][2], acc[mt][nt][3]);
        }
    }
}

// ---------------------------------------------------------------------------
// kernel 2: scores  E = exp(q k^T / 32), fused row-sums into L (atomic)
// ---------------------------------------------------------------------------
__global__ void __launch_bounds__(THREADS, 2)
scores_kernel(const bf16* __restrict__ qb, const bf16* __restrict__ kb,
              bf16* eb, float* lb) {
    extern __shared__ __align__(16) bf16 smem[];
    const int bz = blockIdx.z;
    const int bm = blockIdx.y * 128;
    const int bn = blockIdx.x * 128;

    const bf16* A = qb + (size_t)bz * SEQ * DQK;
    const bf16* B = kb + (size_t)bz * SEQ * DQK;
    bf16* C = eb + (size_t)bz * SEQ * SEQ;

    float acc[4][8][4];
#pragma unroll
    for (int mt = 0; mt < 4; mt++)
#pragma unroll
        for (int nt = 0; nt < 8; nt++)
#pragma unroll
            for (int i = 0; i < 4; i++) acc[mt][nt][i] = 0.0f;

    gemm_body<2>(A, B, DQK, DQK, bm, bn, smem, acc);

    const int lane = threadIdx.x & 31;
    const int warp = threadIdx.x >> 5;
    const int wm = warp >> 1, wn = warp & 1;
    const int g = lane >> 2, t2 = (lane & 3) * 2;
    const float sc = 0.03125f;  // 1/sqrt(1024)
#pragma unroll
    for (int mt = 0; mt < 4; mt++) {
        int r = bm + wm * 64 + mt * 16 + g;
        float s0 = 0.0f, s1 = 0.0f;
#pragma unroll
        for (int nt = 0; nt < 8; nt++) {
            int c = bn + wn * 64 + nt * 8 + t2;
            float e0 = __expf(acc[mt][nt][0] * sc);
            float e1 = __expf(acc[mt][nt][1] * sc);
            float e2 = __expf(acc[mt][nt][2] * sc);
            float e3 = __expf(acc[mt][nt][3] * sc);
            *(__nv_bfloat162*)(C + (size_t)r * SEQ + c) =
                __floats2bfloat162_rn(e0, e1);
            *(__nv_bfloat162*)(C + (size_t)(r + 8) * SEQ + c) =
                __floats2bfloat162_rn(e2, e3);
            s0 += e0 + e1;
            s1 += e2 + e3;
        }
        s0 += __shfl_xor_sync(0xffffffffu, s0, 1);
        s0 += __shfl_xor_sync(0xffffffffu, s0, 2);
        s1 += __shfl_xor_sync(0xffffffffu, s1, 1);
        s1 += __shfl_xor_sync(0xffffffffu, s1, 2);
        if ((lane & 3) == 0) {
            atomicAdd(&lb[(size_t)bz * SEQ + r], s0);
            atomicAdd(&lb[(size_t)bz * SEQ + r + 8], s1);
        }
    }
}

// ---------------------------------------------------------------------------
// kernel 3: out = (E @ v) / L + x
// ---------------------------------------------------------------------------
__global__ void __launch_bounds__(THREADS, 2)
pv_kernel(const bf16* __restrict__ eb, const bf16* __restrict__ vb,
          const float* __restrict__ x, const float* __restrict__ lb,
          float* out) {
    extern __shared__ __align__(16) bf16 smem[];
    const int bz = blockIdx.z;
    const int bm = blockIdx.y * 128;
    const int bn = blockIdx.x * 128;

    const bf16* A = eb + (size_t)bz * SEQ * SEQ;
    const bf16* B = vb + (size_t)bz * SEQ * DV;
    const float* X = x + (size_t)bz * SEQ * DV;
    float* C = out + (size_t)bz * SEQ * DV;

    float acc[4][8][4];
#pragma unroll
    for (int mt = 0; mt < 4; mt++)
#pragma unroll
        for (int nt = 0; nt < 8; nt++)
#pragma unroll
            for (int i = 0; i < 4; i++) acc[mt][nt][i] = 0.0f;

    gemm_body<1>(A, B, SEQ, DV, bm, bn, smem, acc);

    const int lane = threadIdx.x & 31;
    const int warp = threadIdx.x >> 5;
    const int wm = warp >> 1, wn = warp & 1;
    const int g = lane >> 2, t2 = (lane & 3) * 2;
#pragma unroll
    for (int mt = 0; mt < 4; mt++) {
        int r0 = bm + wm * 64 + mt * 16 + g;
        float il0 = 1.0f / lb[(size_t)bz * SEQ + r0];
        float il1 = 1.0f / lb[(size_t)bz * SEQ + r0 + 8];
#pragma unroll
        for (int nt = 0; nt < 8; nt++) {
            int c = bn + wn * 64 + nt * 8 + t2;
            float2 x0 = *(const float2*)(X + (size_t)r0 * DV + c);
            float2 x1 = *(const float2*)(X + (size_t)(r0 + 8) * DV + c);
            float2 o0 = make_float2(acc[mt][nt][0] * il0 + x0.x,
                                    acc[mt][nt][1] * il0 + x0.y);
            float2 o1 = make_float2(acc[mt][nt][2] * il1 + x1.x,
                                    acc[mt][nt][3] * il1 + x1.y);
            *(float2*)(C + (size_t)r0 * DV + c)       = o0;
            *(float2*)(C + (size_t)(r0 + 8) * DV + c) = o1;
        }
    }
}

// ---------------------------------------------------------------------------
// launcher (4 launches)
// ---------------------------------------------------------------------------
extern "C" void kernel_launch(void* const* d_in, const int* in_sizes, int n_in,
                              void* d_out, int out_size) {
    const float* x  = (const float*)d_in[0];
    const float* y  = (const float*)d_in[1];
    const float* Wq = (const float*)d_in[2];
    const float* Wk = (const float*)d_in[3];
    const float* Wv = (const float*)d_in[4];
    float* out = (float*)d_out;

    void *xb, *yb, *wq, *wk, *wv, *qb, *kb, *vb, *eb, *lb;
    cudaGetSymbolAddress(&xb, g_xb);
    cudaGetSymbolAddress(&yb, g_yb);
    cudaGetSymbolAddress(&wq, g_wq);
    cudaGetSymbolAddress(&wk, g_wk);
    cudaGetSymbolAddress(&wv, g_wv);
    cudaGetSymbolAddress(&qb, g_qb);
    cudaGetSymbolAddress(&kb, g_kb);
    cudaGetSymbolAddress(&vb, g_vb);
    cudaGetSymbolAddress(&eb, g_e);
    cudaGetSymbolAddress(&lb, g_l);

    const int M = BATCH * SEQ;  // 32768

    cudaFuncSetAttribute(proj3_kernel,
                         cudaFuncAttributeMaxDynamicSharedMemorySize, SMEM_BYTES);
    cudaFuncSetAttribute(scores_kernel,
                         cudaFuncAttributeMaxDynamicSharedMemorySize, SMEM_BYTES);
    cudaFuncSetAttribute(pv_kernel,
                         cudaFuncAttributeMaxDynamicSharedMemorySize, SMEM_BYTES);

    // 0: converts + zero L
    cvt_all<<<(CVT_TOTAL + 255) / 256, 256>>>(
        x, y, Wq, Wk, Wv, (bf16*)xb, (bf16*)yb, (bf16*)wq, (bf16*)wk,
        (bf16*)wv, (float*)lb);

    // 1: fused projections (12 n-slots x 256 m-tiles)
    proj3_kernel<<<dim3(12, M / 128, 1), THREADS, SMEM_BYTES>>>(
        (const bf16*)xb, (const bf16*)yb, (const bf16*)wq, (const bf16*)wk,
        (const bf16*)wv, (bf16*)qb, (bf16*)kb, (bf16*)vb);

    // 2: scores
    scores_kernel<<<dim3(SEQ / 128, SEQ / 128, BATCH), THREADS, SMEM_BYTES>>>(
        (const bf16*)qb, (const bf16*)kb, (bf16*)eb, (float*)lb);

    // 3: pv + epilogue
    pv_kernel<<<dim3(DV / 128, SEQ / 128, BATCH), THREADS, SMEM_BYTES>>>(
        (const bf16*)eb, (const bf16*)vb, x, (const float*)lb, out);
}

// round 16
// speedup vs baseline: 1.0037x; 1.0037x over previous
#include <cuda_runtime.h>
#include <cuda_bf16.h>
#include <math.h>
#include <stdint.h>

// ============================================================================
// CrossAttention, 4 launches total.
//   0) cvt_all: x,y,Wq,Wk,Wv -> bf16  +  zero L      (one kernel, segments)
//   1) proj3:   q=x@Wq, k=y@Wk, v=y@Wv               (one fused launch, 12 slots)
//   2) scores:  E = exp(q k^T / 32) + row-sums L     (no max-sub; scores small)
//   3) pv:      out = (E @ v) / L + x                (fp32 out)
// GEMM core = R14 champion (CTA 128x128, 4 warps, warp tile 64x64, K-tile 64,
// 3-stage cp.async, sync -> kk0 ldsm -> cp.async -> MMA loop).
// R16: single variable vs R14 — co-resident CTA phase stagger only.
// Shapes: B=16, S=2048, IN=1024, DQK=256, DV=1024
// ============================================================================

#define BATCH 16
#define SEQ   2048
#define INDIM 1024
#define DQK   256
#define DV    1024

typedef __nv_bfloat16 bf16;

// scratch
__device__ __align__(16) bf16 g_xb[(size_t)BATCH * SEQ * INDIM];
__device__ __align__(16) bf16 g_yb[(size_t)BATCH * SEQ * INDIM];
__device__ __align__(16) bf16 g_wq[INDIM * DQK];
__device__ __align__(16) bf16 g_wk[INDIM * DQK];
__device__ __align__(16) bf16 g_wv[INDIM * DV];
__device__ __align__(16) bf16 g_qb[(size_t)BATCH * SEQ * DQK];
__device__ __align__(16) bf16 g_kb[(size_t)BATCH * SEQ * DQK];
__device__ __align__(16) bf16 g_vb[(size_t)BATCH * SEQ * DV];
__device__ __align__(16) bf16 g_e [(size_t)BATCH * SEQ * SEQ];
__device__ __align__(16) float g_l[(size_t)BATCH * SEQ];

// ---------------------------------------------------------------------------
// fused convert + L-zero kernel (compile-time segment bounds)
// ---------------------------------------------------------------------------
#define X4_  (BATCH * SEQ * INDIM / 4)  // 8,388,608
#define WQ4_ (INDIM * DQK / 4)          // 65,536
#define WV4_ (INDIM * DV / 4)           // 262,144
#define L4_  (BATCH * SEQ / 4)          // 8,192
#define CVT_TOTAL (2 * X4_ + 2 * WQ4_ + WV4_ + L4_)

__global__ void cvt_all(const float* __restrict__ x,
                        const float* __restrict__ y,
                        const float* __restrict__ Wq,
                        const float* __restrict__ Wk,
                        const float* __restrict__ Wv,
                        bf16* xb, bf16* yb, bf16* wq, bf16* wk, bf16* wv,
                        float* lb) {
    int i = blockIdx.x * blockDim.x + threadIdx.x;
    if (i >= CVT_TOTAL) return;
    if (i >= 2 * X4_ + 2 * WQ4_ + WV4_) {  // zero L
        int j = i - (2 * X4_ + 2 * WQ4_ + WV4_);
        ((float4*)lb)[j] = make_float4(0.f, 0.f, 0.f, 0.f);
        return;
    }
    const float* src;
    bf16* dst;
    int j;
    if (i < X4_) { src = x; dst = xb; j = i; }
    else if (i < 2 * X4_) { src = y; dst = yb; j = i - X4_; }
    else if (i < 2 * X4_ + WQ4_) { src = Wq; dst = wq; j = i - 2 * X4_; }
    else if (i < 2 * X4_ + 2 * WQ4_) { src = Wk; dst = wk; j = i - 2 * X4_ - WQ4_; }
    else { src = Wv; dst = wv; j = i - 2 * X4_ - 2 * WQ4_; }
    float4 f = ((const float4*)src)[j];
    __nv_bfloat162* d = (__nv_bfloat162*)dst + 2 * (size_t)j;
    d[0] = __floats2bfloat162_rn(f.x, f.y);
    d[1] = __floats2bfloat162_rn(f.z, f.w);
}

// ---------------------------------------------------------------------------
// primitives
// ---------------------------------------------------------------------------
__device__ __forceinline__ void ldsm_x4(uint32_t* r, uint32_t addr) {
    asm volatile("ldmatrix.sync.aligned.m8n8.x4.shared.b16 {%0,%1,%2,%3}, [%4];"
                 : "=r"(r[0]), "=r"(r[1]), "=r"(r[2]), "=r"(r[3]) : "r"(addr));
}
__device__ __forceinline__ void ldsm_x4t(uint32_t* r, uint32_t addr) {
    asm volatile(
        "ldmatrix.sync.aligned.m8n8.x4.trans.shared.b16 {%0,%1,%2,%3}, [%4];"
        : "=r"(r[0]), "=r"(r[1]), "=r"(r[2]), "=r"(r[3]) : "r"(addr));
}
__device__ __forceinline__ void mma_bf16(float* c, const uint32_t* a,
                                         const uint32_t* b) {
    asm volatile(
        "mma.sync.aligned.m16n8k16.row.col.f32.bf16.bf16.f32 "
        "{%0,%1,%2,%3}, {%4,%5,%6,%7}, {%8,%9}, {%0,%1,%2,%3};"
        : "+f"(c[0]), "+f"(c[1]), "+f"(c[2]), "+f"(c[3])
        : "r"(a[0]), "r"(a[1]), "r"(a[2]), "r"(a[3]), "r"(b[0]), "r"(b[1]));
}
__device__ __forceinline__ void cp16(uint32_t dst, const void* src) {
    asm volatile("cp.async.cg.shared.global [%0], [%1], 16;"
                 :: "r"(dst), "l"(src));
}

// ---------------------------------------------------------------------------
// shared GEMM mainloop: acc += A[bm:bm+128, :K] * B   (R14 champion schedule)
//   BKIND 1: B bf16 k-major [K][N]  (ldsm x4 trans)
//   BKIND 2: B bf16 n-major [N][K]  (ldsm x4)
// 128 threads, warp grid 2(m) x 2(n), warp tile 64x64, K-tile 64,
// 3-stage cp.async, race-free early issue, fragment double-buffer.
// Order per tile: sync -> kk0 ldsm -> cp.async burst -> MMA loop.
// ---------------------------------------------------------------------------
#define SA_STRIDE 72      // [128][64+8]
#define SB_STRIDE_K 136   // [64][128+8]
#define SB_STRIDE_N 72    // [128][64+8]
#define ASZ (128 * SA_STRIDE)   // 9216 elems
#define BSZ (128 * SB_STRIDE_N) // 9216 elems (>= 64*136 = 8704)
#define NSTAGE 3
#define SMEM_BYTES (NSTAGE * (ASZ + BSZ) * 2)   // 110,592 B
#define THREADS 128

template <int BKIND>
__device__ __forceinline__ void gemm_body(
    const bf16* __restrict__ A, const bf16* __restrict__ B,
    int K, int ldb, int bm, int bn, bf16* smem, float acc[4][8][4]) {
    const int t    = threadIdx.x;
    const int lane = t & 31;
    const int warp = t >> 5;
    const int wm   = warp >> 1;
    const int wn   = warp & 1;
    const int l15  = lane & 15;

    // R16 single variable: co-resident CTA phase stagger. Wave slots bid and
    // bid+148 share an SM; odd (slot/148) parity delays ~800 cyc once so the
    // two CTAs' per-tile barriers run anti-phased instead of locking.
    {
        int slot = blockIdx.x + gridDim.x * (blockIdx.y + gridDim.y * blockIdx.z);
        if ((slot / 148) & 1) {
            float d = 1.0f + lane;
#pragma unroll 1
            for (int i = 0; i < 200; i++)
                asm volatile("add.f32 %0, %0, 0f3F800000;" : "+f"(d));
            if (d == -1.0f) ((volatile bf16*)smem)[0] = (bf16)d;  // keep live
        }
    }

    const uint32_t shA_u = (uint32_t)__cvta_generic_to_shared(smem);
    const uint32_t shB_u =
        (uint32_t)__cvta_generic_to_shared(smem + NSTAGE * ASZ);

    const uint32_t a_off =
        (uint32_t)((wm * 64 + l15) * SA_STRIDE + (lane >> 4) * 8);
    uint32_t b_off;
    if (BKIND == 2) {
        int m = lane >> 3;
        b_off = (uint32_t)((wn * 64 + (m >> 1) * 8 + (lane & 7)) * SB_STRIDE_N +
                           (m & 1) * 8);
    } else {
        b_off = (uint32_t)(l15 * SB_STRIDE_K + wn * 64 + (lane >> 4) * 8);
    }

    const int NT = K >> 6;

    auto issue = [&](int kt, int buf) {
        const int k0 = kt << 6;
#pragma unroll
        for (int c = 0; c < 8; c++) {
            int idx = t + c * THREADS;
            int row = idx >> 3, col = (idx & 7) * 8;
            cp16(shA_u + (buf * ASZ + row * SA_STRIDE + col) * 2,
                 A + (size_t)(bm + row) * K + k0 + col);
        }
        if (BKIND == 1) {
#pragma unroll
            for (int c = 0; c < 8; c++) {
                int idx = t + c * THREADS;
                int kr = idx >> 4, n = (idx & 15) * 8;
                cp16(shB_u + (buf * BSZ + kr * SB_STRIDE_K + n) * 2,
                     B + (size_t)(k0 + kr) * ldb + bn + n);
            }
        } else {
#pragma unroll
            for (int c = 0; c < 8; c++) {
                int idx = t + c * THREADS;
                int row = idx >> 3, col = (idx & 7) * 8;
                cp16(shB_u + (buf * BSZ + row * SB_STRIDE_N + col) * 2,
                     B + (size_t)(bn + row) * ldb + k0 + col);
            }
        }
        asm volatile("cp.async.commit_group;");
    };

    auto load_frag = [&](uint32_t bufA, uint32_t bufB, int kk,
                         uint32_t a[4][4], uint32_t b[8][2]) {
#pragma unroll
        for (int mt = 0; mt < 4; mt++)
            ldsm_x4(a[mt], bufA + (a_off + mt * 16 * SA_STRIDE + kk) * 2);
#pragma unroll
        for (int nt = 0; nt < 8; nt += 2) {
            uint32_t r[4];
            if (BKIND == 2) {
                ldsm_x4(r, bufB + (b_off + nt * 8 * SB_STRIDE_N + kk) * 2);
            } else {
                ldsm_x4t(r, bufB + (b_off + nt * 8 + kk * SB_STRIDE_K) * 2);
            }
            b[nt][0] = r[0]; b[nt][1] = r[1];
            b[nt + 1][0] = r[2]; b[nt + 1][1] = r[3];
        }
    };

    issue(0, 0);
    issue(1, 1);

    for (int kt = 0; kt < NT; kt++) {
        const int buf = kt % 3;
        if (kt + 1 < NT)
            asm volatile("cp.async.wait_group 1;");
        else
            asm volatile("cp.async.wait_group 0;");
        __syncthreads();

        const uint32_t bufA = shA_u + (buf * ASZ) * 2;
        const uint32_t bufB = shB_u + (buf * BSZ) * 2;

        // kk0 fragment loads FIRST (their latency overlaps the cp.async burst
        // below instead of being preceded by it).
        uint32_t afrag[2][4][4];
        uint32_t bfrag[2][8][2];
        load_frag(bufA, bufB, 0, afrag[0], bfrag[0]);

        // race-free early issue: buffer (kt+2)%3 was fully consumed at kt-1.
        if (kt + 2 < NT) issue(kt + 2, (kt + 2) % 3);

#pragma unroll
        for (int ks = 0; ks < 4; ks++) {
            const int cur = ks & 1;
            const int nxt = cur ^ 1;
            if (ks < 3)
                load_frag(bufA, bufB, (ks + 1) * 16, afrag[nxt], bfrag[nxt]);
#pragma unroll
            for (int mt = 0; mt < 4; mt++)
#pragma unroll
                for (int nt = 0; nt < 8; nt++)
                    mma_bf16(acc[mt][nt], afrag[cur][mt], bfrag[cur][nt]);
        }
    }
}

// ---------------------------------------------------------------------------
// kernel 1: fused q/k/v projections.
// grid.x in [0,12): 0-1 -> q n-tiles (DQK/128=2), 2-3 -> k n-tiles,
//                   4-11 -> v n-tiles (DV/128=8).
// grid.y = M/128 m-tiles.
// ---------------------------------------------------------------------------
__global__ void __launch_bounds__(THREADS, 2)
proj3_kernel(const bf16* __restrict__ xb, const bf16* __restrict__ yb,
             const bf16* __restrict__ wq, const bf16* __restrict__ wk,
             const bf16* __restrict__ wv,
             bf16* qb, bf16* kb, bf16* vb) {
    extern __shared__ __align__(16) bf16 smem[];
    const int gx = blockIdx.x;
    const int bm = blockIdx.y * 128;

    const bf16 *A, *B;
    bf16* C;
    int ldn, bn;
    if (gx < 2)      { A = xb; B = wq; C = qb; ldn = DQK; bn = gx * 128; }
    else if (gx < 4) { A = yb; B = wk; C = kb; ldn = DQK; bn = (gx - 2) * 128; }
    else             { A = yb; B = wv; C = vb; ldn = DV;  bn = (gx - 4) * 128; }

    float acc[4][8][4];
#pragma unroll
    for (int mt = 0; mt < 4; mt++)
#pragma unroll
        for (int nt = 0; nt < 8; nt++)
#pragma unroll
            for (int i = 0; i < 4; i++) acc[mt][nt][i] = 0.0f;

    gemm_body<1>(A, B, INDIM, ldn, bm, bn, smem, acc);

    const int lane = threadIdx.x & 31;
    const int warp = threadIdx.x >> 5;
    const int wm = warp >> 1, wn = warp & 1;
    const int g = lane >> 2, t2 = (lane & 3) * 2;
#pragma unroll
    for (int mt = 0; mt < 4; mt++) {
        int r = bm + wm * 64 + mt * 16 + g;
#pragma unroll
        for (int nt = 0; nt < 8; nt++) {
            int c = bn + wn * 64 + nt * 8 + t2;
            *(__nv_bfloat162*)(C + (size_t)r * ldn + c) =
                __floats2bfloat162_rn(acc[mt][nt][0], acc[mt][nt][1]);
            *(__nv_bfloat162*)(C + (size_t)(r + 8) * ldn + c) =
                __floats2bfloat162_rn(acc[mt][nt][2], acc[mt][nt][3]);
        }
    }
}

// ---------------------------------------------------------------------------
// kernel 2: scores  E = exp(q k^T / 32), fused row-sums into L (atomic)
// ---------------------------------------------------------------------------
__global__ void __launch_bounds__(THREADS, 2)
scores_kernel(const bf16* __restrict__ qb, const bf16* __restrict__ kb,
              bf16* eb, float* lb) {
    extern __shared__ __align__(16) bf16 smem[];
    const int bz = blockIdx.z;
    const int bm = blockIdx.y * 128;
    const int bn = blockIdx.x * 128;

    const bf16* A = qb + (size_t)bz * SEQ * DQK;
    const bf16* B = kb + (size_t)bz * SEQ * DQK;
    bf16* C = eb + (size_t)bz * SEQ * SEQ;

    float acc[4][8][4];
#pragma unroll
    for (int mt = 0; mt < 4; mt++)
#pragma unroll
        for (int nt = 0; nt < 8; nt++)
#pragma unroll
            for (int i = 0; i < 4; i++) acc[mt][nt][i] = 0.0f;

    gemm_body<2>(A, B, DQK, DQK, bm, bn, smem, acc);

    const int lane = threadIdx.x & 31;
    const int warp = threadIdx.x >> 5;
    const int wm = warp >> 1, wn = warp & 1;
    const int g = lane >> 2, t2 = (lane & 3) * 2;
    const float sc = 0.03125f;  // 1/sqrt(1024)
#pragma unroll
    for (int mt = 0; mt < 4; mt++) {
        int r = bm + wm * 64 + mt * 16 + g;
        float s0 = 0.0f, s1 = 0.0f;
#pragma unroll
        for (int nt = 0; nt < 8; nt++) {
            int c = bn + wn * 64 + nt * 8 + t2;
            float e0 = __expf(acc[mt][nt][0] * sc);
            float e1 = __expf(acc[mt][nt][1] * sc);
            float e2 = __expf(acc[mt][nt][2] * sc);
            float e3 = __expf(acc[mt][nt][3] * sc);
            *(__nv_bfloat162*)(C + (size_t)r * SEQ + c) =
                __floats2bfloat162_rn(e0, e1);
            *(__nv_bfloat162*)(C + (size_t)(r + 8) * SEQ + c) =
                __floats2bfloat162_rn(e2, e3);
            s0 += e0 + e1;
            s1 += e2 + e3;
        }
        s0 += __shfl_xor_sync(0xffffffffu, s0, 1);
        s0 += __shfl_xor_sync(0xffffffffu, s0, 2);
        s1 += __shfl_xor_sync(0xffffffffu, s1, 1);
        s1 += __shfl_xor_sync(0xffffffffu, s1, 2);
        if ((lane & 3) == 0) {
            atomicAdd(&lb[(size_t)bz * SEQ + r], s0);
            atomicAdd(&lb[(size_t)bz * SEQ + r + 8], s1);
        }
    }
}

// ---------------------------------------------------------------------------
// kernel 3: out = (E @ v) / L + x
// ---------------------------------------------------------------------------
__global__ void __launch_bounds__(THREADS, 2)
pv_kernel(const bf16* __restrict__ eb, const bf16* __restrict__ vb,
          const float* __restrict__ x, const float* __restrict__ lb,
          float* out) {
    extern __shared__ __align__(16) bf16 smem[];
    const int bz = blockIdx.z;
    const int bm = blockIdx.y * 128;
    const int bn = blockIdx.x * 128;

    const bf16* A = eb + (size_t)bz * SEQ * SEQ;
    const bf16* B = vb + (size_t)bz * SEQ * DV;
    const float* X = x + (size_t)bz * SEQ * DV;
    float* C = out + (size_t)bz * SEQ * DV;

    float acc[4][8][4];
#pragma unroll
    for (int mt = 0; mt < 4; mt++)
#pragma unroll
        for (int nt = 0; nt < 8; nt++)
#pragma unroll
            for (int i = 0; i < 4; i++) acc[mt][nt][i] = 0.0f;

    gemm_body<1>(A, B, SEQ, DV, bm, bn, smem, acc);

    const int lane = threadIdx.x & 31;
    const int warp = threadIdx.x >> 5;
    const int wm = warp >> 1, wn = warp & 1;
    const int g = lane >> 2, t2 = (lane & 3) * 2;
#pragma unroll
    for (int mt = 0; mt < 4; mt++) {
        int r0 = bm + wm * 64 + mt * 16 + g;
        float il0 = 1.0f / lb[(size_t)bz * SEQ + r0];
        float il1 = 1.0f / lb[(size_t)bz * SEQ + r0 + 8];
#pragma unroll
        for (int nt = 0; nt < 8; nt++) {
            int c = bn + wn * 64 + nt * 8 + t2;
            float2 x0 = *(const float2*)(X + (size_t)r0 * DV + c);
            float2 x1 = *(const float2*)(X + (size_t)(r0 + 8) * DV + c);
            float2 o0 = make_float2(acc[mt][nt][0] * il0 + x0.x,
                                    acc[mt][nt][1] * il0 + x0.y);
            float2 o1 = make_float2(acc[mt][nt][2] * il1 + x1.x,
                                    acc[mt][nt][3] * il1 + x1.y);
            *(float2*)(C + (size_t)r0 * DV + c)       = o0;
            *(float2*)(C + (size_t)(r0 + 8) * DV + c) = o1;
        }
    }
}

// ---------------------------------------------------------------------------
// launcher (4 launches)
// ---------------------------------------------------------------------------
extern "C" void kernel_launch(void* const* d_in, const int* in_sizes, int n_in,
                              void* d_out, int out_size) {
    const float* x  = (const float*)d_in[0];
    const float* y  = (const float*)d_in[1];
    const float* Wq = (const float*)d_in[2];
    const float* Wk = (const float*)d_in[3];
    const float* Wv = (const float*)d_in[4];
    float* out = (float*)d_out;

    void *xb, *yb, *wq, *wk, *wv, *qb, *kb, *vb, *eb, *lb;
    cudaGetSymbolAddress(&xb, g_xb);
    cudaGetSymbolAddress(&yb, g_yb);
    cudaGetSymbolAddress(&wq, g_wq);
    cudaGetSymbolAddress(&wk, g_wk);
    cudaGetSymbolAddress(&wv, g_wv);
    cudaGetSymbolAddress(&qb, g_qb);
    cudaGetSymbolAddress(&kb, g_kb);
    cudaGetSymbolAddress(&vb, g_vb);
    cudaGetSymbolAddress(&eb, g_e);
    cudaGetSymbolAddress(&lb, g_l);

    const int M = BATCH * SEQ;  // 32768

    cudaFuncSetAttribute(proj3_kernel,
                         cudaFuncAttributeMaxDynamicSharedMemorySize, SMEM_BYTES);
    cudaFuncSetAttribute(scores_kernel,
                         cudaFuncAttributeMaxDynamicSharedMemorySize, SMEM_BYTES);
    cudaFuncSetAttribute(pv_kernel,
                         cudaFuncAttributeMaxDynamicSharedMemorySize, SMEM_BYTES);

    // 0: converts + zero L
    cvt_all<<<(CVT_TOTAL + 255) / 256, 256>>>(
        x, y, Wq, Wk, Wv, (bf16*)xb, (bf16*)yb, (bf16*)wq, (bf16*)wk,
        (bf16*)wv, (float*)lb);

    // 1: fused projections (12 n-slots x 256 m-tiles)
    proj3_kernel<<<dim3(12, M / 128, 1), THREADS, SMEM_BYTES>>>(
        (const bf16*)xb, (const bf16*)yb, (const bf16*)wq, (const bf16*)wk,
        (const bf16*)wv, (bf16*)qb, (bf16*)kb, (bf16*)vb);

    // 2: scores
    scores_kernel<<<dim3(SEQ / 128, SEQ / 128, BATCH), THREADS, SMEM_BYTES>>>(
        (const bf16*)qb, (const bf16*)kb, (bf16*)eb, (float*)lb);

    // 3: pv + epilogue
    pv_kernel<<<dim3(DV / 128, SEQ / 128, BATCH), THREADS, SMEM_BYTES>>>(
        (const bf16*)eb, (const bf16*)vb, x, (const float*)lb, out);
}

// round 17
// speedup vs baseline: 1.0391x; 1.0353x over previous
#include <cuda_runtime.h>
#include <cuda_bf16.h>
#include <math.h>
#include <stdint.h>

// ============================================================================
// CrossAttention, 4 launches total (converged champion = R14 configuration).
//   0) cvt_all: x,y,Wq,Wk,Wv -> bf16  +  zero L      (one kernel, segments)
//   1) proj3:   q=x@Wq, k=y@Wk, v=y@Wv               (one fused launch, 12 slots)
//   2) scores:  E = exp(q k^T / 32) + row-sums L     (no max-sub; scores small)
//   3) pv:      out = (E @ v) / L + x                (fp32 out)
// GEMM core: CTA 128x128, 4 warps, warp tile 64x64, K-tile 64, 3-stage
// cp.async, race-free early issue, fragment double-buffer, kk0 fragment
// loads issued BEFORE the next cp.async burst (tile-head bubble removal).
// Shapes: B=16, S=2048, IN=1024, DQK=256, DV=1024
// ============================================================================

#define BATCH 16
#define SEQ   2048
#define INDIM 1024
#define DQK   256
#define DV    1024

typedef __nv_bfloat16 bf16;

// scratch
__device__ __align__(16) bf16 g_xb[(size_t)BATCH * SEQ * INDIM];
__device__ __align__(16) bf16 g_yb[(size_t)BATCH * SEQ * INDIM];
__device__ __align__(16) bf16 g_wq[INDIM * DQK];
__device__ __align__(16) bf16 g_wk[INDIM * DQK];
__device__ __align__(16) bf16 g_wv[INDIM * DV];
__device__ __align__(16) bf16 g_qb[(size_t)BATCH * SEQ * DQK];
__device__ __align__(16) bf16 g_kb[(size_t)BATCH * SEQ * DQK];
__device__ __align__(16) bf16 g_vb[(size_t)BATCH * SEQ * DV];
__device__ __align__(16) bf16 g_e [(size_t)BATCH * SEQ * SEQ];
__device__ __align__(16) float g_l[(size_t)BATCH * SEQ];

// ---------------------------------------------------------------------------
// fused convert + L-zero kernel (compile-time segment bounds)
// ---------------------------------------------------------------------------
#define X4_  (BATCH * SEQ * INDIM / 4)  // 8,388,608
#define WQ4_ (INDIM * DQK / 4)          // 65,536
#define WV4_ (INDIM * DV / 4)           // 262,144
#define L4_  (BATCH * SEQ / 4)          // 8,192
#define CVT_TOTAL (2 * X4_ + 2 * WQ4_ + WV4_ + L4_)

__global__ void cvt_all(const float* __restrict__ x,
                        const float* __restrict__ y,
                        const float* __restrict__ Wq,
                        const float* __restrict__ Wk,
                        const float* __restrict__ Wv,
                        bf16* xb, bf16* yb, bf16* wq, bf16* wk, bf16* wv,
                        float* lb) {
    int i = blockIdx.x * blockDim.x + threadIdx.x;
    if (i >= CVT_TOTAL) return;
    if (i >= 2 * X4_ + 2 * WQ4_ + WV4_) {  // zero L
        int j = i - (2 * X4_ + 2 * WQ4_ + WV4_);
        ((float4*)lb)[j] = make_float4(0.f, 0.f, 0.f, 0.f);
        return;
    }
    const float* src;
    bf16* dst;
    int j;
    if (i < X4_) { src = x; dst = xb; j = i; }
    else if (i < 2 * X4_) { src = y; dst = yb; j = i - X4_; }
    else if (i < 2 * X4_ + WQ4_) { src = Wq; dst = wq; j = i - 2 * X4_; }
    else if (i < 2 * X4_ + 2 * WQ4_) { src = Wk; dst = wk; j = i - 2 * X4_ - WQ4_; }
    else { src = Wv; dst = wv; j = i - 2 * X4_ - 2 * WQ4_; }
    float4 f = ((const float4*)src)[j];
    __nv_bfloat162* d = (__nv_bfloat162*)dst + 2 * (size_t)j;
    d[0] = __floats2bfloat162_rn(f.x, f.y);
    d[1] = __floats2bfloat162_rn(f.z, f.w);
}

// ---------------------------------------------------------------------------
// primitives
// ---------------------------------------------------------------------------
__device__ __forceinline__ void ldsm_x4(uint32_t* r, uint32_t addr) {
    asm volatile("ldmatrix.sync.aligned.m8n8.x4.shared.b16 {%0,%1,%2,%3}, [%4];"
                 : "=r"(r[0]), "=r"(r[1]), "=r"(r[2]), "=r"(r[3]) : "r"(addr));
}
__device__ __forceinline__ void ldsm_x4t(uint32_t* r, uint32_t addr) {
    asm volatile(
        "ldmatrix.sync.aligned.m8n8.x4.trans.shared.b16 {%0,%1,%2,%3}, [%4];"
        : "=r"(r[0]), "=r"(r[1]), "=r"(r[2]), "=r"(r[3]) : "r"(addr));
}
__device__ __forceinline__ void mma_bf16(float* c, const uint32_t* a,
                                         const uint32_t* b) {
    asm volatile(
        "mma.sync.aligned.m16n8k16.row.col.f32.bf16.bf16.f32 "
        "{%0,%1,%2,%3}, {%4,%5,%6,%7}, {%8,%9}, {%0,%1,%2,%3};"
        : "+f"(c[0]), "+f"(c[1]), "+f"(c[2]), "+f"(c[3])
        : "r"(a[0]), "r"(a[1]), "r"(a[2]), "r"(a[3]), "r"(b[0]), "r"(b[1]));
}
__device__ __forceinline__ void cp16(uint32_t dst, const void* src) {
    asm volatile("cp.async.cg.shared.global [%0], [%1], 16;"
                 :: "r"(dst), "l"(src));
}

// ---------------------------------------------------------------------------
// shared GEMM mainloop: acc += A[bm:bm+128, :K] * B
//   BKIND 1: B bf16 k-major [K][N]  (ldsm x4 trans)
//   BKIND 2: B bf16 n-major [N][K]  (ldsm x4)
// 128 threads, warp grid 2(m) x 2(n), warp tile 64x64, K-tile 64,
// 3-stage cp.async, race-free early issue, fragment double-buffer.
// Order per tile: sync -> kk0 ldsm -> cp.async burst -> MMA loop.
// ---------------------------------------------------------------------------
#define SA_STRIDE 72      // [128][64+8]
#define SB_STRIDE_K 136   // [64][128+8]
#define SB_STRIDE_N 72    // [128][64+8]
#define ASZ (128 * SA_STRIDE)   // 9216 elems
#define BSZ (128 * SB_STRIDE_N) // 9216 elems (>= 64*136 = 8704)
#define NSTAGE 3
#define SMEM_BYTES (NSTAGE * (ASZ + BSZ) * 2)   // 110,592 B
#define THREADS 128

template <int BKIND>
__device__ __forceinline__ void gemm_body(
    const bf16* __restrict__ A, const bf16* __restrict__ B,
    int K, int ldb, int bm, int bn, bf16* smem, float acc[4][8][4]) {
    const int t    = threadIdx.x;
    const int lane = t & 31;
    const int warp = t >> 5;
    const int wm   = warp >> 1;
    const int wn   = warp & 1;
    const int l15  = lane & 15;

    const uint32_t shA_u = (uint32_t)__cvta_generic_to_shared(smem);
    const uint32_t shB_u =
        (uint32_t)__cvta_generic_to_shared(smem + NSTAGE * ASZ);

    const uint32_t a_off =
        (uint32_t)((wm * 64 + l15) * SA_STRIDE + (lane >> 4) * 8);
    uint32_t b_off;
    if (BKIND == 2) {
        int m = lane >> 3;
        b_off = (uint32_t)((wn * 64 + (m >> 1) * 8 + (lane & 7)) * SB_STRIDE_N +
                           (m & 1) * 8);
    } else {
        b_off = (uint32_t)(l15 * SB_STRIDE_K + wn * 64 + (lane >> 4) * 8);
    }

    const int NT = K >> 6;

    auto issue = [&](int kt, int buf) {
        const int k0 = kt << 6;
#pragma unroll
        for (int c = 0; c < 8; c++) {
            int idx = t + c * THREADS;
            int row = idx >> 3, col = (idx & 7) * 8;
            cp16(shA_u + (buf * ASZ + row * SA_STRIDE + col) * 2,
                 A + (size_t)(bm + row) * K + k0 + col);
        }
        if (BKIND == 1) {
#pragma unroll
            for (int c = 0; c < 8; c++) {
                int idx = t + c * THREADS;
                int kr = idx >> 4, n = (idx & 15) * 8;
                cp16(shB_u + (buf * BSZ + kr * SB_STRIDE_K + n) * 2,
                     B + (size_t)(k0 + kr) * ldb + bn + n);
            }
        } else {
#pragma unroll
            for (int c = 0; c < 8; c++) {
                int idx = t + c * THREADS;
                int row = idx >> 3, col = (idx & 7) * 8;
                cp16(shB_u + (buf * BSZ + row * SB_STRIDE_N + col) * 2,
                     B + (size_t)(bn + row) * ldb + k0 + col);
            }
        }
        asm volatile("cp.async.commit_group;");
    };

    auto load_frag = [&](uint32_t bufA, uint32_t bufB, int kk,
                         uint32_t a[4][4], uint32_t b[8][2]) {
#pragma unroll
        for (int mt = 0; mt < 4; mt++)
            ldsm_x4(a[mt], bufA + (a_off + mt * 16 * SA_STRIDE + kk) * 2);
#pragma unroll
        for (int nt = 0; nt < 8; nt += 2) {
            uint32_t r[4];
            if (BKIND == 2) {
                ldsm_x4(r, bufB + (b_off + nt * 8 * SB_STRIDE_N + kk) * 2);
            } else {
                ldsm_x4t(r, bufB + (b_off + nt * 8 + kk * SB_STRIDE_K) * 2);
            }
            b[nt][0] = r[0]; b[nt][1] = r[1];
            b[nt + 1][0] = r[2]; b[nt + 1][1] = r[3];
        }
    };

    issue(0, 0);
    issue(1, 1);

    for (int kt = 0; kt < NT; kt++) {
        const int buf = kt % 3;
        if (kt + 1 < NT)
            asm volatile("cp.async.wait_group 1;");
        else
            asm volatile("cp.async.wait_group 0;");
        __syncthreads();

        const uint32_t bufA = shA_u + (buf * ASZ) * 2;
        const uint32_t bufB = shB_u + (buf * BSZ) * 2;

        // kk0 fragment loads FIRST (their latency overlaps the cp.async burst
        // below instead of being preceded by it).
        uint32_t afrag[2][4][4];
        uint32_t bfrag[2][8][2];
        load_frag(bufA, bufB, 0, afrag[0], bfrag[0]);

        // race-free early issue: buffer (kt+2)%3 was fully consumed at kt-1.
        if (kt + 2 < NT) issue(kt + 2, (kt + 2) % 3);

#pragma unroll
        for (int ks = 0; ks < 4; ks++) {
            const int cur = ks & 1;
            const int nxt = cur ^ 1;
            if (ks < 3)
                load_frag(bufA, bufB, (ks + 1) * 16, afrag[nxt], bfrag[nxt]);
#pragma unroll
            for (int mt = 0; mt < 4; mt++)
#pragma unroll
                for (int nt = 0; nt < 8; nt++)
                    mma_bf16(acc[mt][nt], afrag[cur][mt], bfrag[cur][nt]);
        }
    }
}

// ---------------------------------------------------------------------------
// kernel 1: fused q/k/v projections.
// grid.x in [0,12): 0-1 -> q n-tiles (DQK/128=2), 2-3 -> k n-tiles,
//                   4-11 -> v n-tiles (DV/128=8).
// grid.y = M/128 m-tiles.
// ---------------------------------------------------------------------------
__global__ void __launch_bounds__(THREADS, 2)
proj3_kernel(const bf16* __restrict__ xb, const bf16* __restrict__ yb,
             const bf16* __restrict__ wq, const bf16* __restrict__ wk,
             const bf16* __restrict__ wv,
             bf16* qb, bf16* kb, bf16* vb) {
    extern __shared__ __align__(16) bf16 smem[];
    const int gx = blockIdx.x;
    const int bm = blockIdx.y * 128;

    const bf16 *A, *B;
    bf16* C;
    int ldn, bn;
    if (gx < 2)      { A = xb; B = wq; C = qb; ldn = DQK; bn = gx * 128; }
    else if (gx < 4) { A = yb; B = wk; C = kb; ldn = DQK; bn = (gx - 2) * 128; }
    else             { A = yb; B = wv; C = vb; ldn = DV;  bn = (gx - 4) * 128; }

    float acc[4][8][4];
#pragma unroll
    for (int mt = 0; mt < 4; mt++)
#pragma unroll
        for (int nt = 0; nt < 8; nt++)
#pragma unroll
            for (int i = 0; i < 4; i++) acc[mt][nt][i] = 0.0f;

    gemm_body<1>(A, B, INDIM, ldn, bm, bn, smem, acc);

    const int lane = threadIdx.x & 31;
    const int warp = threadIdx.x >> 5;
    const int wm = warp >> 1, wn = warp & 1;
    const int g = lane >> 2, t2 = (lane & 3) * 2;
#pragma unroll
    for (int mt = 0; mt < 4; mt++) {
        int r = bm + wm * 64 + mt * 16 + g;
#pragma unroll
        for (int nt = 0; nt < 8; nt++) {
            int c = bn + wn * 64 + nt * 8 + t2;
            *(__nv_bfloat162*)(C + (size_t)r * ldn + c) =
                __floats2bfloat162_rn(acc[mt][nt][0], acc[mt][nt][1]);
            *(__nv_bfloat162*)(C + (size_t)(r + 8) * ldn + c) =
                __floats2bfloat162_rn(acc[mt][nt][2], acc[mt][nt][3]);
        }
    }
}

// ---------------------------------------------------------------------------
// kernel 2: scores  E = exp(q k^T / 32), fused row-sums into L (atomic)
// ---------------------------------------------------------------------------
__global__ void __launch_bounds__(THREADS, 2)
scores_kernel(const bf16* __restrict__ qb, const bf16* __restrict__ kb,
              bf16* eb, float* lb) {
    extern __shared__ __align__(16) bf16 smem[];
    const int bz = blockIdx.z;
    const int bm = blockIdx.y * 128;
    const int bn = blockIdx.x * 128;

    const bf16* A = qb + (size_t)bz * SEQ * DQK;
    const bf16* B = kb + (size_t)bz * SEQ * DQK;
    bf16* C = eb + (size_t)bz * SEQ * SEQ;

    float acc[4][8][4];
#pragma unroll
    for (int mt = 0; mt < 4; mt++)
#pragma unroll
        for (int nt = 0; nt < 8; nt++)
#pragma unroll
            for (int i = 0; i < 4; i++) acc[mt][nt][i] = 0.0f;

    gemm_body<2>(A, B, DQK, DQK, bm, bn, smem, acc);

    const int lane = threadIdx.x & 31;
    const int warp = threadIdx.x >> 5;
    const int wm = warp >> 1, wn = warp & 1;
    const int g = lane >> 2, t2 = (lane & 3) * 2;
    const float sc = 0.03125f;  // 1/sqrt(1024)
#pragma unroll
    for (int mt = 0; mt < 4; mt++) {
        int r = bm + wm * 64 + mt * 16 + g;
        float s0 = 0.0f, s1 = 0.0f;
#pragma unroll
        for (int nt = 0; nt < 8; nt++) {
            int c = bn + wn * 64 + nt * 8 + t2;
            float e0 = __expf(acc[mt][nt][0] * sc);
            float e1 = __expf(acc[mt][nt][1] * sc);
            float e2 = __expf(acc[mt][nt][2] * sc);
            float e3 = __expf(acc[mt][nt][3] * sc);
            *(__nv_bfloat162*)(C + (size_t)r * SEQ + c) =
                __floats2bfloat162_rn(e0, e1);
            *(__nv_bfloat162*)(C + (size_t)(r + 8) * SEQ + c) =
                __floats2bfloat162_rn(e2, e3);
            s0 += e0 + e1;
            s1 += e2 + e3;
        }
        s0 += __shfl_xor_sync(0xffffffffu, s0, 1);
        s0 += __shfl_xor_sync(0xffffffffu, s0, 2);
        s1 += __shfl_xor_sync(0xffffffffu, s1, 1);
        s1 += __shfl_xor_sync(0xffffffffu, s1, 2);
        if ((lane & 3) == 0) {
            atomicAdd(&lb[(size_t)bz * SEQ + r], s0);
            atomicAdd(&lb[(size_t)bz * SEQ + r + 8], s1);
        }
    }
}

// ---------------------------------------------------------------------------
// kernel 3: out = (E @ v) / L + x
// ---------------------------------------------------------------------------
__global__ void __launch_bounds__(THREADS, 2)
pv_kernel(const bf16* __restrict__ eb, const bf16* __restrict__ vb,
          const float* __restrict__ x, const float* __restrict__ lb,
          float* out) {
    extern __shared__ __align__(16) bf16 smem[];
    const int bz = blockIdx.z;
    const int bm = blockIdx.y * 128;
    const int bn = blockIdx.x * 128;

    const bf16* A = eb + (size_t)bz * SEQ * SEQ;
    const bf16* B = vb + (size_t)bz * SEQ * DV;
    const float* X = x + (size_t)bz * SEQ * DV;
    float* C = out + (size_t)bz * SEQ * DV;

    float acc[4][8][4];
#pragma unroll
    for (int mt = 0; mt < 4; mt++)
#pragma unroll
        for (int nt = 0; nt < 8; nt++)
#pragma unroll
            for (int i = 0; i < 4; i++) acc[mt][nt][i] = 0.0f;

    gemm_body<1>(A, B, SEQ, DV, bm, bn, smem, acc);

    const int lane = threadIdx.x & 31;
    const int warp = threadIdx.x >> 5;
    const int wm = warp >> 1, wn = warp & 1;
    const int g = lane >> 2, t2 = (lane & 3) * 2;
#pragma unroll
    for (int mt = 0; mt < 4; mt++) {
        int r0 = bm + wm * 64 + mt * 16 + g;
        float il0 = 1.0f / lb[(size_t)bz * SEQ + r0];
        float il1 = 1.0f / lb[(size_t)bz * SEQ + r0 + 8];
#pragma unroll
        for (int nt = 0; nt < 8; nt++) {
            int c = bn + wn * 64 + nt * 8 + t2;
            float2 x0 = *(const float2*)(X + (size_t)r0 * DV + c);
            float2 x1 = *(const float2*)(X + (size_t)(r0 + 8) * DV + c);
            float2 o0 = make_float2(acc[mt][nt][0] * il0 + x0.x,
                                    acc[mt][nt][1] * il0 + x0.y);
            float2 o1 = make_float2(acc[mt][nt][2] * il1 + x1.x,
                                    acc[mt][nt][3] * il1 + x1.y);
            *(float2*)(C + (size_t)r0 * DV + c)       = o0;
            *(float2*)(C + (size_t)(r0 + 8) * DV + c) = o1;
        }
    }
}

// ---------------------------------------------------------------------------
// launcher (4 launches)
// ---------------------------------------------------------------------------
extern "C" void kernel_launch(void* const* d_in, const int* in_sizes, int n_in,
                              void* d_out, int out_size) {
    const float* x  = (const float*)d_in[0];
    const float* y  = (const float*)d_in[1];
    const float* Wq = (const float*)d_in[2];
    const float* Wk = (const float*)d_in[3];
    const float* Wv = (const float*)d_in[4];
    float* out = (float*)d_out;

    void *xb, *yb, *wq, *wk, *wv, *qb, *kb, *vb, *eb, *lb;
    cudaGetSymbolAddress(&xb, g_xb);
    cudaGetSymbolAddress(&yb, g_yb);
    cudaGetSymbolAddress(&wq, g_wq);
    cudaGetSymbolAddress(&wk, g_wk);
    cudaGetSymbolAddress(&wv, g_wv);
    cudaGetSymbolAddress(&qb, g_qb);
    cudaGetSymbolAddress(&kb, g_kb);
    cudaGetSymbolAddress(&vb, g_vb);
    cudaGetSymbolAddress(&eb, g_e);
    cudaGetSymbolAddress(&lb, g_l);

    const int M = BATCH * SEQ;  // 32768

    cudaFuncSetAttribute(proj3_kernel,
                         cudaFuncAttributeMaxDynamicSharedMemorySize, SMEM_BYTES);
    cudaFuncSetAttribute(scores_kernel,
                         cudaFuncAttributeMaxDynamicSharedMemorySize, SMEM_BYTES);
    cudaFuncSetAttribute(pv_kernel,
                         cudaFuncAttributeMaxDynamicSharedMemorySize, SMEM_BYTES);

    // 0: converts + zero L
    cvt_all<<<(CVT_TOTAL + 255) / 256, 256>>>(
        x, y, Wq, Wk, Wv, (bf16*)xb, (bf16*)yb, (bf16*)wq, (bf16*)wk,
        (bf16*)wv, (float*)lb);

    // 1: fused projections (12 n-slots x 256 m-tiles)
    proj3_kernel<<<dim3(12, M / 128, 1), THREADS, SMEM_BYTES>>>(
        (const bf16*)xb, (const bf16*)yb, (const bf16*)wq, (const bf16*)wk,
        (const bf16*)wv, (bf16*)qb, (bf16*)kb, (bf16*)vb);

    // 2: scores
    scores_kernel<<<dim3(SEQ / 128, SEQ / 128, BATCH), THREADS, SMEM_BYTES>>>(
        (const bf16*)qb, (const bf16*)kb, (bf16*)eb, (float*)lb);

    // 3: pv + epilogue
    pv_kernel<<<dim3(DV / 128, SEQ / 128, BATCH), THREADS, SMEM_BYTES>>>(
        (const bf16*)eb, (const bf16*)vb, x, (const float*)lb, out);
}